// round 2
// baseline (speedup 1.0000x reference)
#include <cuda_runtime.h>
#include <math.h>

#define BB 16
#define CC 64
#define NN 1024
#define NH 4
#define FF 15
#define FH 60
#define KK 9
#define ALPHA 0.2f

// ---------------- scratch (device globals; no allocation) ----------------
__device__ __align__(16) float g_h[BB*CC*NN];      // [b][c][n]
__device__ __align__(16) float g_sq[BB*NN];
__device__ __align__(16) float g_dist[(size_t)BB*NN*NN];   // 64MB
__device__ __align__(16) int   g_idx[BB*NN*KK];
__device__ __align__(16) float g_Wh[BB*NN*FH];     // [b][n][60] (head-major 4x15)
__device__ __align__(16) float g_f1[BB*NN*NH];
__device__ __align__(16) float g_f2[BB*NN*NH];
__device__ __align__(16) float g_den[BB*NN*NH];
__device__ __align__(16) float g_hcat[BB*NN*FH];
__device__ __align__(16) float g_Who[BB*NN*CC];    // [b][n][64]
__device__ __align__(16) float g_f1o[BB*NN];
__device__ __align__(16) float g_f2o[BB*NN];
__device__ __align__(16) float g_deno[BB*NN];

// ---------------- K1: L2 normalize over C ----------------
__global__ void k_norm(const float* __restrict__ x) {
    int t = blockIdx.x * 256 + threadIdx.x;          // [0, B*N)
    int b = t >> 10, n = t & 1023;
    const float* xp = x + (size_t)b * CC * NN + n;
    float s = 0.f;
#pragma unroll
    for (int c = 0; c < CC; c++) { float v = xp[c * NN]; s += v * v; }
    float nrm = fmaxf(sqrtf(s), 1e-12f);
    float r = 1.0f / nrm;
    float s2 = 0.f;
    float* hp = g_h + (size_t)b * CC * NN + n;
#pragma unroll
    for (int c = 0; c < CC; c++) {
        float v = xp[c * NN] * r;
        hp[c * NN] = v;
        s2 += v * v;
    }
    g_sq[t] = s2;
}

// ---------------- K2: gram / dist matrix (fp32, f32x2-packed FFMA) ----------------
extern __shared__ float smem_g[];
__global__ __launch_bounds__(256) void k_gram() {
    float* As = smem_g;                // [64][128]
    float* Bs = smem_g + 64 * 128;     // [64][128]
    int b = blockIdx.z;
    int i0 = blockIdx.y * 128, j0 = blockIdx.x * 128;
    int t = threadIdx.x;
    const float* hb = g_h + (size_t)b * CC * NN;
#pragma unroll
    for (int r = 0; r < 8; r++) {
        int lin = t + r * 256;               // float4 index into [64][32]
        int c = lin >> 5, pos = lin & 31;
        *(float4*)(As + c * 128 + pos * 4) = *(const float4*)(hb + c * NN + i0 + pos * 4);
        *(float4*)(Bs + c * 128 + pos * 4) = *(const float4*)(hb + c * NN + j0 + pos * 4);
    }
    __syncthreads();
    int tx = t & 15, ty = t >> 4;
    const float* ap = As + ty * 8;
    const float* bp = Bs + tx * 8;
    unsigned long long acc[8][4];
#pragma unroll
    for (int ii = 0; ii < 8; ii++)
#pragma unroll
        for (int jj = 0; jj < 4; jj++) acc[ii][jj] = 0ull;

#pragma unroll 8
    for (int c = 0; c < 64; c++) {
        float4 a0 = *(const float4*)(ap + c * 128);
        float4 a1 = *(const float4*)(ap + c * 128 + 4);
        ulonglong2 b0 = *(const ulonglong2*)(bp + c * 128);
        ulonglong2 b1 = *(const ulonglong2*)(bp + c * 128 + 4);
        unsigned long long bb[4] = { b0.x, b0.y, b1.x, b1.y };
        float av[8] = { a0.x, a0.y, a0.z, a0.w, a1.x, a1.y, a1.z, a1.w };
#pragma unroll
        for (int ii = 0; ii < 8; ii++) {
            unsigned long long pa;
            asm("mov.b64 %0, {%1, %1};" : "=l"(pa) : "f"(av[ii]));
#pragma unroll
            for (int jj = 0; jj < 4; jj++)
                asm("fma.rn.f32x2 %0, %1, %2, %0;" : "+l"(acc[ii][jj]) : "l"(pa), "l"(bb[jj]));
        }
    }
    const float* sqb = g_sq + b * NN;
    float sj[8];
#pragma unroll
    for (int jj = 0; jj < 8; jj++) sj[jj] = sqb[j0 + tx * 8 + jj];
#pragma unroll
    for (int ii = 0; ii < 8; ii++) {
        int i = i0 + ty * 8 + ii;
        float si = sqb[i];
        float o[8];
#pragma unroll
        for (int jj = 0; jj < 4; jj++) {
            unsigned long long v = acc[ii][jj];
            float lo = __uint_as_float((unsigned)(v & 0xffffffffull));
            float hi = __uint_as_float((unsigned)(v >> 32));
            o[2 * jj]     = fmaf(-2.f, lo, si) + sj[2 * jj];
            o[2 * jj + 1] = fmaf(-2.f, hi, si) + sj[2 * jj + 1];
        }
        float* dst = g_dist + ((size_t)(b * NN + i)) * NN + j0 + tx * 8;
        *(float4*)dst       = make_float4(o[0], o[1], o[2], o[3]);
        *(float4*)(dst + 4) = make_float4(o[4], o[5], o[6], o[7]);
    }
}

// ---------------- K_top9: warp per row, u64 keys, exact tie-break ----------------
__global__ void k_top9() {
    int warp = threadIdx.x >> 5, lane = threadIdx.x & 31;
    int row = blockIdx.x * 8 + warp;            // [0, B*N)
    const float* dr = g_dist + (size_t)row * NN;
    unsigned long long best[9];
#pragma unroll
    for (int q = 0; q < 9; q++) best[q] = 0xFFFFFFFFFFFFFFFFull;
    for (int j = lane; j < NN; j += 32) {
        float d = dr[j];
        unsigned u = __float_as_uint(d);
        u = (u & 0x80000000u) ? ~u : (u | 0x80000000u);   // order-preserving map
        unsigned long long key = ((unsigned long long)u << 32) | (unsigned)j;
        if (key < best[8]) {
            best[8] = key;
#pragma unroll
            for (int q = 8; q > 0; q--) {
                unsigned long long a = best[q - 1], c = best[q];
                best[q - 1] = (a < c) ? a : c;
                best[q]     = (a < c) ? c : a;
            }
        }
    }
    int p = 0;
    for (int r = 0; r < 9; r++) {
        unsigned long long v = best[p];
        unsigned long long m = v;
#pragma unroll
        for (int off = 16; off; off >>= 1) {
            unsigned long long o = __shfl_xor_sync(0xFFFFFFFFu, m, off);
            m = (o < m) ? o : m;
        }
        if (v == m) p++;                         // keys unique (contain j)
        if (lane == 0) g_idx[row * 9 + r] = (int)(m & 0xFFFFFFFFull);
    }
}

// ---------------- K3: Wh (4 heads), f1/f2, zero den ----------------
__global__ void k3(const float* __restrict__ Wheads, const float* __restrict__ aheads) {
    __shared__ float Wc[CC * FH];
    __shared__ float as[NH * 2 * FF];
    int t = threadIdx.x;
    int b = blockIdx.x >> 2;
    int n0 = (blockIdx.x & 3) * 256;
    for (int idx = t; idx < NH * CC * FF; idx += 256) {
        int h = idx / (CC * FF); int rem = idx % (CC * FF);
        int c = rem / FF; int f = rem % FF;
        Wc[c * FH + h * FF + f] = Wheads[idx];
    }
    if (t < NH * 2 * FF) as[t] = aheads[t];
    __syncthreads();
    int n = n0 + t;
    const float* hp = g_h + (size_t)b * CC * NN + n;
    float acc[FH];
#pragma unroll
    for (int f = 0; f < FH; f++) acc[f] = 0.f;
    for (int c = 0; c < CC; c++) {
        float hc = hp[c * NN];
#pragma unroll
        for (int f = 0; f < FH; f++) acc[f] = fmaf(hc, Wc[c * FH + f], acc[f]);
    }
    size_t row = (size_t)b * NN + n;
    float4* wout = (float4*)(g_Wh + row * FH);
#pragma unroll
    for (int q = 0; q < FH / 4; q++)
        wout[q] = make_float4(acc[4 * q], acc[4 * q + 1], acc[4 * q + 2], acc[4 * q + 3]);
#pragma unroll
    for (int h = 0; h < NH; h++) {
        float f1 = 0.f, f2 = 0.f;
#pragma unroll
        for (int f = 0; f < FF; f++) {
            f1 = fmaf(acc[h * FF + f], as[h * 2 * FF + f], f1);
            f2 = fmaf(acc[h * FF + f], as[h * 2 * FF + FF + f], f2);
        }
        g_f1[row * NH + h] = f1;
        g_f2[row * NH + h] = f2;
        g_den[row * NH + h] = 0.f;
    }
}

// ---------------- K4: column denominators (heads), scatter atomics ----------------
__global__ void k4() {
    int row = blockIdx.x * 256 + threadIdx.x;     // b*N + i
    int bbase = row & ~1023;
    float4 f1v = *(const float4*)(g_f1 + (size_t)row * 4);
    const int* ip = g_idx + row * 9;
#pragma unroll
    for (int k = 0; k < KK; k++) {
        int jr = bbase + ip[k];
        float4 f2v = *(const float4*)(g_f2 + (size_t)jr * 4);
        float* dp = g_den + (size_t)jr * 4;
        float e0 = f1v.x + f2v.x; e0 = e0 > 0.f ? e0 : ALPHA * e0;
        float e1 = f1v.y + f2v.y; e1 = e1 > 0.f ? e1 : ALPHA * e1;
        float e2 = f1v.z + f2v.z; e2 = e2 > 0.f ? e2 : ALPHA * e2;
        float e3 = f1v.w + f2v.w; e3 = e3 > 0.f ? e3 : ALPHA * e3;
        atomicAdd(dp + 0, expf(e0));
        atomicAdd(dp + 1, expf(e1));
        atomicAdd(dp + 2, expf(e2));
        atomicAdd(dp + 3, expf(e3));
    }
}

// ---------------- K5: head aggregation + ELU -> hcat ----------------
__global__ void k5() {
    int t = threadIdx.x;                 // 240 = 4 nodes x 60
    int local = t / FH, c = t % FH;
    int row = blockIdx.x * 4 + local;    // b*N + i
    int bbase = row & ~1023;
    int h = c / FF;
    const int* ip = g_idx + row * 9;
    float f1v = g_f1[(size_t)row * 4 + h];
    float acc = 0.f;
#pragma unroll
    for (int k = 0; k < KK; k++) {
        int jr = bbase + ip[k];
        float e = f1v + g_f2[(size_t)jr * 4 + h];
        e = e > 0.f ? e : ALPHA * e;
        float w = expf(e) / g_den[(size_t)jr * 4 + h];
        acc = fmaf(w, g_Wh[(size_t)jr * FH + c], acc);
    }
    g_hcat[(size_t)row * FH + c] = acc > 0.f ? acc : expm1f(acc);
}

// ---------------- K6: W_out GEMM + f1o/f2o, zero deno ----------------
__global__ void k6(const float* __restrict__ Wout, const float* __restrict__ aout) {
    __shared__ float Wo[FH * CC];
    __shared__ float av[2 * CC];
    int t = threadIdx.x;
    int b = blockIdx.x >> 2;
    int n0 = (blockIdx.x & 3) * 256;
    for (int idx = t; idx < FH * CC; idx += 256) Wo[idx] = Wout[idx];
    if (t < 2 * CC) av[t] = aout[t];
    __syncthreads();
    int n = n0 + t;
    size_t row = (size_t)b * NN + n;
    const float* hr = g_hcat + row * FH;
    float acc[CC];
#pragma unroll
    for (int o = 0; o < CC; o++) acc[o] = 0.f;
#pragma unroll
    for (int c4 = 0; c4 < FH / 4; c4++) {
        float4 hv = *(const float4*)(hr + c4 * 4);
        float hs[4] = { hv.x, hv.y, hv.z, hv.w };
#pragma unroll
        for (int q = 0; q < 4; q++) {
            int c = c4 * 4 + q;
#pragma unroll
            for (int o = 0; o < CC; o++) acc[o] = fmaf(hs[q], Wo[c * CC + o], acc[o]);
        }
    }
    float4* wout4 = (float4*)(g_Who + row * CC);
#pragma unroll
    for (int q = 0; q < CC / 4; q++)
        wout4[q] = make_float4(acc[4 * q], acc[4 * q + 1], acc[4 * q + 2], acc[4 * q + 3]);
    float f1 = 0.f, f2 = 0.f;
#pragma unroll
    for (int o = 0; o < CC; o++) {
        f1 = fmaf(acc[o], av[o], f1);
        f2 = fmaf(acc[o], av[CC + o], f2);
    }
    g_f1o[row] = f1;
    g_f2o[row] = f2;
    g_deno[row] = 0.f;
}

// ---------------- K7: output-layer denominators ----------------
__global__ void k7() {
    int row = blockIdx.x * 256 + threadIdx.x;
    int bbase = row & ~1023;
    float f1 = g_f1o[row];
    const int* ip = g_idx + row * 9;
#pragma unroll
    for (int k = 0; k < KK; k++) {
        int jr = bbase + ip[k];
        float e = f1 + g_f2o[jr];
        e = e > 0.f ? e : ALPHA * e;
        atomicAdd(g_deno + jr, expf(e));
    }
}

// ---------------- K8: out-aggregate + ELU + LReLU + conv1x1 + BN + residual ----------------
__global__ void k8(const float* __restrict__ x, const float* __restrict__ cw,
                   const float* __restrict__ cb, const float* __restrict__ gamma,
                   const float* __restrict__ beta, float* __restrict__ out) {
    __shared__ float cws[CC * 65];
    __shared__ float ys[32 * 65];
    __shared__ float ws[32 * KK];
    __shared__ int   js[32 * KK];
    int t = threadIdx.x;
    int b = blockIdx.x >> 5;
    int n0 = (blockIdx.x & 31) * 32;
    for (int idx = t; idx < CC * CC; idx += 256) {
        int o = idx >> 6, c = idx & 63;
        cws[o * 65 + c] = cw[idx];
    }
    for (int idx = t; idx < 32 * KK; idx += 256) {
        int node = idx / KK, k = idx % KK;
        int row = b * NN + n0 + node;
        int jr = b * NN + g_idx[row * 9 + k];
        float e = g_f1o[row] + g_f2o[jr];
        e = e > 0.f ? e : ALPHA * e;
        ws[idx] = expf(e) / g_deno[jr];
        js[idx] = jr;
    }
    __syncthreads();
#pragma unroll
    for (int p = 0; p < 8; p++) {
        int idx = t + p * 256;
        int node = idx >> 6, c = idx & 63;
        float acc = 0.f;
#pragma unroll
        for (int k = 0; k < KK; k++)
            acc = fmaf(ws[node * KK + k], g_Who[(size_t)js[node * KK + k] * CC + c], acc);
        float e = acc > 0.f ? acc : expm1f(acc);   // ELU
        ys[node * 65 + c] = e > 0.f ? e : 0.01f * e; // LeakyReLU(0.01)
    }
    __syncthreads();
    int node = t & 31, og = t >> 5;
    float bnr = 1.0f / sqrtf(1.0f + 1e-5f);
#pragma unroll
    for (int p = 0; p < 8; p++) {
        int o = og * 8 + p;
        float s = cb[o];
        const float* yr = ys + node * 65;
        const float* cr = cws + o * 65;
#pragma unroll
        for (int c = 0; c < CC; c++) s = fmaf(cr[c], yr[c], s);
        s = s * bnr * gamma[o] + beta[o];
        size_t oidx = ((size_t)(b * CC + o)) * NN + n0 + node;
        out[oidx] = s + x[oidx];
    }
}

// ---------------- launch ----------------
extern "C" void kernel_launch(void* const* d_in, const int* in_sizes, int n_in,
                              void* d_out, int out_size) {
    const float* x      = (const float*)d_in[0];
    const float* Wheads = (const float*)d_in[1];
    const float* aheads = (const float*)d_in[2];
    const float* Wout   = (const float*)d_in[3];
    const float* aout   = (const float*)d_in[4];
    const float* convw  = (const float*)d_in[5];
    const float* convb  = (const float*)d_in[6];
    const float* gamma  = (const float*)d_in[7];
    const float* beta   = (const float*)d_in[8];
    float* out = (float*)d_out;

    static bool attr_set = false;
    if (!attr_set) {
        cudaFuncSetAttribute(k_gram, cudaFuncAttributeMaxDynamicSharedMemorySize, 65536);
        attr_set = true;
    }

    k_norm<<<BB * NN / 256, 256>>>(x);
    k_gram<<<dim3(8, 8, BB), 256, 65536>>>();
    k_top9<<<BB * NN / 8, 256>>>();
    k3<<<BB * 4, 256>>>(Wheads, aheads);
    k4<<<BB * NN / 256, 256>>>();
    k5<<<BB * NN / 4, 240>>>();
    k6<<<BB * 4, 256>>>(Wout, aout);
    k7<<<BB * NN / 256, 256>>>();
    k8<<<BB * 32, 256>>>(x, convw, convb, gamma, beta, out);
}

// round 3
// speedup vs baseline: 1.2255x; 1.2255x over previous
#include <cuda_runtime.h>
#include <math.h>

#define BB 16
#define CC 64
#define NN 1024
#define NH 4
#define FF 15
#define FH 60
#define KK 9
#define ALPHA 0.2f

typedef unsigned long long u64;

// ---------------- scratch (device globals; no allocation) ----------------
__device__ __align__(16) float g_h[BB*CC*NN];      // [b][c][n]
__device__ __align__(16) float g_sq[BB*NN];
__device__ __align__(16) int   g_idx[BB*NN*KK];
__device__ __align__(16) float g_Wh[BB*NN*FH];     // [b][n][60] (head-major 4x15)
__device__ __align__(16) float g_f1[BB*NN*NH];
__device__ __align__(16) float g_f2[BB*NN*NH];
__device__ __align__(16) float g_den[BB*NN*NH];
__device__ __align__(16) float g_ew[BB*NN*KK*NH];  // cached exp per edge per head
__device__ __align__(16) float g_hcat[BB*NN*FH];
__device__ __align__(16) float g_Who[BB*NN*CC];    // [b][n][64]
__device__ __align__(16) float g_f1o[BB*NN];
__device__ __align__(16) float g_f2o[BB*NN];
__device__ __align__(16) float g_deno[BB*NN];
__device__ __align__(16) float g_ewo[BB*NN*KK];

// ---------------- K1: L2 normalize over C ----------------
__global__ void k_norm(const float* __restrict__ x) {
    int t = blockIdx.x * 256 + threadIdx.x;          // [0, B*N)
    int b = t >> 10, n = t & 1023;
    const float* xp = x + (size_t)b * CC * NN + n;
    float s = 0.f;
#pragma unroll
    for (int c = 0; c < CC; c++) { float v = xp[c * NN]; s += v * v; }
    float nrm = fmaxf(sqrtf(s), 1e-12f);
    float r = 1.0f / nrm;
    float s2 = 0.f;
    float* hp = g_h + (size_t)b * CC * NN + n;
#pragma unroll
    for (int c = 0; c < CC; c++) {
        float v = xp[c * NN] * r;
        hp[c * NN] = v;
        s2 += v * v;
    }
    g_sq[t] = s2;
}

// ---------------- K2: fused gram + top-9 ----------------
// Block: 128 rows (i), streams all 1024 j in chunks of 128.
// Each thread keeps a register-resident sorted top-9 (u64 keys) for half a row.
#define DPAD 140
extern __shared__ float smem_g[];
__global__ __launch_bounds__(256) void k_gramtop() {
    float* As = smem_g;                 // [64][128]
    float* Bs = smem_g + 64 * 128;      // [64][128]
    float* Ds = smem_g + 2 * 64 * 128;  // [128][DPAD]
    int b = blockIdx.y;
    int i0 = blockIdx.x * 128;
    int t = threadIdx.x;
    const float* hb = g_h + (size_t)b * CC * NN;
    const float* sqb = g_sq + b * NN;

#pragma unroll
    for (int r = 0; r < 8; r++) {
        int lin = t + r * 256;               // float4 index into [64][32]
        int c = lin >> 5, pos = lin & 31;
        *(float4*)(As + c * 128 + pos * 4) = *(const float4*)(hb + c * NN + i0 + pos * 4);
    }
    int tx = t & 15, ty = t >> 4;
    float si[8];
#pragma unroll
    for (int ii = 0; ii < 8; ii++) si[ii] = sqb[i0 + ty * 8 + ii];

    // persistent per-thread top-9 (ascending)
    u64 best[9];
#pragma unroll
    for (int q = 0; q < 9; q++) best[q] = 0xFFFFFFFFFFFFFFFFull;

    int myrow = t >> 1, half = t & 1;

    for (int jc = 0; jc < 8; jc++) {
        int j0 = jc * 128;
        __syncthreads();   // previous-chunk Bs/Ds consumers done
#pragma unroll
        for (int r = 0; r < 8; r++) {
            int lin = t + r * 256;
            int c = lin >> 5, pos = lin & 31;
            *(float4*)(Bs + c * 128 + pos * 4) = *(const float4*)(hb + c * NN + j0 + pos * 4);
        }
        __syncthreads();

        const float* ap = As + ty * 8;
        const float* bp = Bs + tx * 8;
        u64 acc[8][4];
#pragma unroll
        for (int ii = 0; ii < 8; ii++)
#pragma unroll
            for (int jj = 0; jj < 4; jj++) acc[ii][jj] = 0ull;

#pragma unroll 8
        for (int c = 0; c < 64; c++) {
            float4 a0 = *(const float4*)(ap + c * 128);
            float4 a1 = *(const float4*)(ap + c * 128 + 4);
            ulonglong2 b0 = *(const ulonglong2*)(bp + c * 128);
            ulonglong2 b1 = *(const ulonglong2*)(bp + c * 128 + 4);
            u64 bb[4] = { b0.x, b0.y, b1.x, b1.y };
            float av[8] = { a0.x, a0.y, a0.z, a0.w, a1.x, a1.y, a1.z, a1.w };
#pragma unroll
            for (int ii = 0; ii < 8; ii++) {
                u64 pa;
                asm("mov.b64 %0, {%1, %1};" : "=l"(pa) : "f"(av[ii]));
#pragma unroll
                for (int jj = 0; jj < 4; jj++)
                    asm("fma.rn.f32x2 %0, %1, %2, %0;" : "+l"(acc[ii][jj]) : "l"(pa), "l"(bb[jj]));
            }
        }
        float sj[8];
#pragma unroll
        for (int jj = 0; jj < 8; jj++) sj[jj] = sqb[j0 + tx * 8 + jj];
#pragma unroll
        for (int ii = 0; ii < 8; ii++) {
            float o[8];
#pragma unroll
            for (int jj = 0; jj < 4; jj++) {
                u64 v = acc[ii][jj];
                float lo = __uint_as_float((unsigned)(v & 0xffffffffull));
                float hi = __uint_as_float((unsigned)(v >> 32));
                o[2 * jj]     = fmaf(-2.f, lo, si[ii]) + sj[2 * jj];
                o[2 * jj + 1] = fmaf(-2.f, hi, si[ii]) + sj[2 * jj + 1];
            }
            float* dst = Ds + (ty * 8 + ii) * DPAD + tx * 8;
            *(float4*)dst       = make_float4(o[0], o[1], o[2], o[3]);
            *(float4*)(dst + 4) = make_float4(o[4], o[5], o[6], o[7]);
        }
        __syncthreads();

        // scan: thread owns (row = t>>1), interleaved half of 128 cols
        const float* drow = Ds + myrow * DPAD + half;
        u64 b8 = best[8];
#pragma unroll 8
        for (int c = 0; c < 64; c++) {
            float d = drow[2 * c];
            unsigned u = __float_as_uint(d);
            u = (u & 0x80000000u) ? ~u : (u | 0x80000000u);   // order-preserving
            u64 key = ((u64)u << 32) | (unsigned)(j0 + 2 * c + half);
            if (key < b8) {
                best[8] = key;
#pragma unroll
                for (int q = 8; q > 0; q--) {
                    u64 a = best[q - 1], cc2 = best[q];
                    best[q - 1] = (a < cc2) ? a : cc2;
                    best[q]     = (a < cc2) ? cc2 : a;
                }
                b8 = best[8];
            }
        }
    }
    __syncthreads();
    // merge the two half-row lists per row (reuse As region as u64 buffer)
    u64* Tp = (u64*)smem_g;
#pragma unroll
    for (int q = 0; q < 9; q++) Tp[t * 9 + q] = best[q];
    __syncthreads();
    if (t < 128) {
        const u64* A  = Tp + (2 * t) * 9;
        const u64* Bl = Tp + (2 * t + 1) * 9;
        int ia = 0, ib = 0;
        int* op = g_idx + ((size_t)(b * NN + i0 + t)) * 9;
#pragma unroll
        for (int q = 0; q < 9; q++) {
            u64 a = A[ia], bb2 = Bl[ib];
            if (a < bb2) { op[q] = (int)(a & 0xFFFFFFFFull); ia++; }
            else         { op[q] = (int)(bb2 & 0xFFFFFFFFull); ib++; }
        }
    }
}

// ---------------- K3: Wh (4 heads), f1/f2, zero den ----------------
// 4 threads per node (one per head); 64 nodes per block -> 256 blocks.
__global__ __launch_bounds__(256) void k3(const float* __restrict__ Wheads,
                                          const float* __restrict__ aheads) {
    __shared__ float Hs[CC * 65];        // [c][n]
    __shared__ float Wc[CC * FH];        // [c][h*15+f]
    __shared__ float as[NH * 2 * FF];
    int t = threadIdx.x;
    int b = blockIdx.x >> 4;
    int n0 = (blockIdx.x & 15) * 64;
    for (int idx = t; idx < NH * CC * FF; idx += 256) {
        int h = idx / (CC * FF); int rem = idx % (CC * FF);
        int c = rem / FF; int f = rem % FF;
        Wc[c * FH + h * FF + f] = Wheads[idx];
    }
    if (t < NH * 2 * FF) as[t] = aheads[t];
    for (int idx = t; idx < CC * 64; idx += 256) {
        int c = idx >> 6, n = idx & 63;
        Hs[c * 65 + n] = g_h[(size_t)b * CC * NN + c * NN + n0 + n];
    }
    __syncthreads();
    int node = t >> 2, h = t & 3;
    size_t row = (size_t)b * NN + n0 + node;
    float acc[FF];
#pragma unroll
    for (int f = 0; f < FF; f++) acc[f] = 0.f;
#pragma unroll 8
    for (int c = 0; c < CC; c++) {
        float hc = Hs[c * 65 + node];
#pragma unroll
        for (int f = 0; f < FF; f++) acc[f] = fmaf(hc, Wc[c * FH + h * FF + f], acc[f]);
    }
    float* wout = g_Wh + row * FH + h * FF;
#pragma unroll
    for (int f = 0; f < FF; f++) wout[f] = acc[f];
    float f1 = 0.f, f2 = 0.f;
#pragma unroll
    for (int f = 0; f < FF; f++) {
        f1 = fmaf(acc[f], as[h * 2 * FF + f], f1);
        f2 = fmaf(acc[f], as[h * 2 * FF + FF + f], f2);
    }
    g_f1[row * NH + h] = f1;
    g_f2[row * NH + h] = f2;
    g_den[row * NH + h] = 0.f;
}

// ---------------- K4: denominators (heads) + exp cache ----------------
__global__ void k4() {
    int row = blockIdx.x * 256 + threadIdx.x;     // b*N + i
    int bbase = row & ~1023;
    float4 f1v = *(const float4*)(g_f1 + (size_t)row * 4);
    const int* ip = g_idx + row * 9;
#pragma unroll
    for (int k = 0; k < KK; k++) {
        int jr = bbase + ip[k];
        float4 f2v = *(const float4*)(g_f2 + (size_t)jr * 4);
        float* dp = g_den + (size_t)jr * 4;
        float e0 = f1v.x + f2v.x; e0 = e0 > 0.f ? e0 : ALPHA * e0;
        float e1 = f1v.y + f2v.y; e1 = e1 > 0.f ? e1 : ALPHA * e1;
        float e2 = f1v.z + f2v.z; e2 = e2 > 0.f ? e2 : ALPHA * e2;
        float e3 = f1v.w + f2v.w; e3 = e3 > 0.f ? e3 : ALPHA * e3;
        float x0 = __expf(e0), x1 = __expf(e1), x2 = __expf(e2), x3 = __expf(e3);
        *(float4*)(g_ew + ((size_t)row * 9 + k) * 4) = make_float4(x0, x1, x2, x3);
        atomicAdd(dp + 0, x0);
        atomicAdd(dp + 1, x1);
        atomicAdd(dp + 2, x2);
        atomicAdd(dp + 3, x3);
    }
}

// ---------------- K5: head aggregation + ELU -> hcat ----------------
__global__ void k5() {
    __shared__ float ws[4 * KK * NH];
    __shared__ int   js[4 * KK];
    int t = threadIdx.x;                 // 240 = 4 nodes x 60
    int row0 = blockIdx.x * 4;
    int bbase = row0 & ~1023;
    if (t < 4 * KK * NH) {
        int local = t / (KK * NH), rem = t % (KK * NH);
        int k = rem >> 2, h = rem & 3;
        int row = row0 + local;
        int jr = bbase + g_idx[row * 9 + k];
        ws[t] = __fdividef(g_ew[((size_t)row * 9 + k) * 4 + h], g_den[(size_t)jr * 4 + h]);
        if (h == 0) js[local * KK + k] = jr;
    }
    __syncthreads();
    int local = t / FH, c = t % FH;
    int row = row0 + local;
    int h = c / FF;
    float acc = 0.f;
#pragma unroll
    for (int k = 0; k < KK; k++)
        acc = fmaf(ws[(local * KK + k) * 4 + h], g_Wh[(size_t)js[local * KK + k] * FH + c], acc);
    g_hcat[(size_t)row * FH + c] = acc > 0.f ? acc : expm1f(acc);
}

// ---------------- K6: W_out GEMM + f1o/f2o, zero deno ----------------
// 4 threads per node (16 outputs each); 64 nodes per block -> 256 blocks.
__global__ __launch_bounds__(256) void k6(const float* __restrict__ Wout,
                                          const float* __restrict__ aout) {
    __shared__ float Hc[64 * 61];        // [node][c]
    __shared__ float Wo[FH * CC];
    __shared__ float av[2 * CC];
    int t = threadIdx.x;
    int b = blockIdx.x >> 4;
    int n0 = (blockIdx.x & 15) * 64;
    for (int idx = t; idx < FH * CC; idx += 256) Wo[idx] = Wout[idx];
    if (t < 2 * CC) av[t] = aout[t];
    for (int idx = t; idx < 64 * FH; idx += 256) {
        int node = idx / FH, c = idx % FH;
        Hc[node * 61 + c] = g_hcat[((size_t)(b * NN + n0 + node)) * FH + c];
    }
    __syncthreads();
    int node = t >> 2, q = t & 3;
    size_t row = (size_t)b * NN + n0 + node;
    float acc[16];
#pragma unroll
    for (int f = 0; f < 16; f++) acc[f] = 0.f;
#pragma unroll 6
    for (int c = 0; c < FH; c++) {
        float hv = Hc[node * 61 + c];
#pragma unroll
        for (int f = 0; f < 16; f++)
            acc[f] = fmaf(hv, Wo[c * CC + q * 16 + f], acc[f]);
    }
    float4* wout4 = (float4*)(g_Who + row * CC + q * 16);
#pragma unroll
    for (int p = 0; p < 4; p++)
        wout4[p] = make_float4(acc[4 * p], acc[4 * p + 1], acc[4 * p + 2], acc[4 * p + 3]);
    float f1 = 0.f, f2 = 0.f;
#pragma unroll
    for (int f = 0; f < 16; f++) {
        f1 = fmaf(acc[f], av[q * 16 + f], f1);
        f2 = fmaf(acc[f], av[CC + q * 16 + f], f2);
    }
#pragma unroll
    for (int off = 1; off < 4; off <<= 1) {
        f1 += __shfl_xor_sync(0xFFFFFFFFu, f1, off);
        f2 += __shfl_xor_sync(0xFFFFFFFFu, f2, off);
    }
    if (q == 0) {
        g_f1o[row] = f1;
        g_f2o[row] = f2;
        g_deno[row] = 0.f;
    }
}

// ---------------- K7: output-layer denominators + exp cache ----------------
__global__ void k7() {
    int row = blockIdx.x * 256 + threadIdx.x;
    int bbase = row & ~1023;
    float f1 = g_f1o[row];
    const int* ip = g_idx + row * 9;
#pragma unroll
    for (int k = 0; k < KK; k++) {
        int jr = bbase + ip[k];
        float e = f1 + g_f2o[jr];
        e = e > 0.f ? e : ALPHA * e;
        float ex = __expf(e);
        g_ewo[(size_t)row * 9 + k] = ex;
        atomicAdd(g_deno + jr, ex);
    }
}

// ---------------- K8: out-aggregate + ELU + LReLU + conv1x1 + BN + residual ----------------
__global__ void k8(const float* __restrict__ x, const float* __restrict__ cw,
                   const float* __restrict__ cb, const float* __restrict__ gamma,
                   const float* __restrict__ beta, float* __restrict__ out) {
    __shared__ float cws[CC * 65];
    __shared__ float ys[32 * 65];
    __shared__ float ws[32 * KK];
    __shared__ int   js[32 * KK];
    int t = threadIdx.x;
    int b = blockIdx.x >> 5;
    int n0 = (blockIdx.x & 31) * 32;
    for (int idx = t; idx < CC * CC; idx += 256) {
        int o = idx >> 6, c = idx & 63;
        cws[o * 65 + c] = cw[idx];
    }
    for (int idx = t; idx < 32 * KK; idx += 256) {
        int node = idx / KK, k = idx % KK;
        int row = b * NN + n0 + node;
        int jr = b * NN + g_idx[row * 9 + k];
        ws[idx] = __fdividef(g_ewo[(size_t)row * 9 + k], g_deno[jr]);
        js[idx] = jr;
    }
    __syncthreads();
#pragma unroll
    for (int p = 0; p < 8; p++) {
        int idx = t + p * 256;
        int node = idx >> 6, c = idx & 63;
        float acc = 0.f;
#pragma unroll
        for (int k = 0; k < KK; k++)
            acc = fmaf(ws[node * KK + k], g_Who[(size_t)js[node * KK + k] * CC + c], acc);
        float e = acc > 0.f ? acc : expm1f(acc);     // ELU
        ys[node * 65 + c] = e > 0.f ? e : 0.01f * e; // LeakyReLU(0.01)
    }
    __syncthreads();
    int node = t & 31, og = t >> 5;
    float bnr = 1.0f / sqrtf(1.0f + 1e-5f);
#pragma unroll
    for (int p = 0; p < 8; p++) {
        int o = og * 8 + p;
        float s = cb[o];
        const float* yr = ys + node * 65;
        const float* cr = cws + o * 65;
#pragma unroll
        for (int c = 0; c < CC; c++) s = fmaf(cr[c], yr[c], s);
        s = s * bnr * gamma[o] + beta[o];
        size_t oidx = ((size_t)(b * CC + o)) * NN + n0 + node;
        out[oidx] = s + x[oidx];
    }
}

// ---------------- launch ----------------
extern "C" void kernel_launch(void* const* d_in, const int* in_sizes, int n_in,
                              void* d_out, int out_size) {
    const float* x      = (const float*)d_in[0];
    const float* Wheads = (const float*)d_in[1];
    const float* aheads = (const float*)d_in[2];
    const float* Wout   = (const float*)d_in[3];
    const float* aout   = (const float*)d_in[4];
    const float* convw  = (const float*)d_in[5];
    const float* convb  = (const float*)d_in[6];
    const float* gamma  = (const float*)d_in[7];
    const float* beta   = (const float*)d_in[8];
    float* out = (float*)d_out;

    const int GT_SMEM = (2 * 64 * 128 + 128 * DPAD) * 4;  // As+Bs+Ds
    static bool attr_set = false;
    if (!attr_set) {
        cudaFuncSetAttribute(k_gramtop, cudaFuncAttributeMaxDynamicSharedMemorySize, GT_SMEM);
        attr_set = true;
    }

    k_norm<<<BB * NN / 256, 256>>>(x);
    k_gramtop<<<dim3(8, BB), 256, GT_SMEM>>>();
    k3<<<BB * 16, 256>>>(Wheads, aheads);
    k4<<<BB * NN / 256, 256>>>();
    k5<<<BB * NN / 4, 240>>>();
    k6<<<BB * 16, 256>>>(Wout, aout);
    k7<<<BB * NN / 256, 256>>>();
    k8<<<BB * 32, 256>>>(x, convw, convb, gamma, beta, out);
}